// round 8
// baseline (speedup 1.0000x reference)
#include <cuda_runtime.h>
#include <math.h>
#include <stdint.h>

// ---------------- problem constants ----------------
#define TS   63
#define BB   256
#define OBSD 512
#define ACTD 32
#define EMBD 1024
#define DETD 1024
#define STOD 256
#define RR   (TS*BB)
#define FEATD (DETD+STOD)   // 1280
#define SN   3584           // sequential S width: [post(512) | gh(3072)]
#define PCTA 112            // persistent CTAs (<= SM count, all resident)

// ---------------- device scratch ----------------
__device__ float g_embh[RR*EMBD];
__device__ float g_emb [RR*EMBD];
__device__ float g_post_emb[RR*2*STOD];        // [RR, 512] (includes post_b)
__device__ float g_feat[RR*FEATD];             // [h | z] per (t,b) row
__device__ float g_H1  [RR*2048];
__device__ float g_pred[RR*OBSD];
__device__ float g_S_all[(size_t)RR*SN];       // per-step [post|gh] projections
__device__ float g_prior[(size_t)RR*512];      // batched prior projections
__device__ float g_hin[(size_t)RR*DETD];       // carried h at input of each step
__device__ float g_G[BB*3*DETD];
__device__ float g_h[BB*DETD];
__device__ float g_kl[RR];
__device__ float g_recon[RR];
__device__ float g_rewl[RR];
// barrier state
__device__ unsigned g_cnt;
__device__ volatile unsigned g_gen;
// weights, pre-transposed to [N,K] (K-major)
__device__ float g_Wh2T[SN*DETD];              // [post_w_h | whh^T]
__device__ float g_bh2[SN];
__device__ float g_priorT[512*DETD];
__device__ float g_encw1T[EMBD*OBSD];
__device__ float g_encw2T[EMBD*EMBD];
__device__ float g_postEmbT[2*STOD*EMBD];
__device__ float g_decw2T[OBSD*EMBD];
__device__ float g_W1fT[2048*FEATD];
__device__ float g_b1f[2048];

__device__ __forceinline__ uint32_t f2tf(float f) {
    uint32_t r;
    asm("cvt.rna.tf32.f32 %0, %1;" : "=r"(r) : "f"(f));
    return r;
}
__device__ __forceinline__ int swz(int r, int k) {
    return r*32 + (k ^ ((r & 7) << 2));
}

// ================= global GEMM (Phases A/C), tile 128x128 =================
__global__ void __launch_bounds__(256) mma_gemm128(
    const float* __restrict__ A, int lda,
    const float* __restrict__ B, int ldb,
    float* __restrict__ C, int ldc,
    const float* __restrict__ bias,
    int K, int relu)
{
    __shared__ __align__(16) uint32_t As[128*32];
    __shared__ __align__(16) uint32_t Bs[128*32];

    const int tid = threadIdx.x;
    const int wid = tid >> 5, lane = tid & 31;
    const int warp_m = wid & 3;
    const int warp_n = wid >> 2;
    const int gid = lane >> 2, tig = lane & 3;
    const long brow = (long)blockIdx.y * 128;
    const long bcol = (long)blockIdx.x * 128;
    const int nch = K >> 5;

    float c[2][8][4];
    #pragma unroll
    for (int im = 0; im < 2; im++)
        #pragma unroll
        for (int in_ = 0; in_ < 8; in_++)
            #pragma unroll
            for (int j = 0; j < 4; j++) c[im][in_][j] = 0.0f;

    int fr[4], fkc[4];
    #pragma unroll
    for (int i = 0; i < 4; i++) {
        int lin = i*256 + tid;
        fr[i]  = lin >> 3;
        fkc[i] = (lin & 7) << 2;
    }

    float4 sA[4], sB[4];
    #pragma unroll
    for (int i = 0; i < 4; i++) {
        sA[i] = *(const float4*)(A + (brow + fr[i])*(long)lda + fkc[i]);
        sB[i] = *(const float4*)(B + (bcol + fr[i])*(long)ldb + fkc[i]);
    }

    for (int cch = 0; cch < nch; cch++) {
        #pragma unroll
        for (int i = 0; i < 4; i++) {
            uint4 t;
            t.x = f2tf(sA[i].x); t.y = f2tf(sA[i].y);
            t.z = f2tf(sA[i].z); t.w = f2tf(sA[i].w);
            *(uint4*)&As[swz(fr[i], fkc[i])] = t;
            uint4 u;
            u.x = f2tf(sB[i].x); u.y = f2tf(sB[i].y);
            u.z = f2tf(sB[i].z); u.w = f2tf(sB[i].w);
            *(uint4*)&Bs[swz(fr[i], fkc[i])] = u;
        }
        __syncthreads();

        if (cch + 1 < nch) {
            int k0 = (cch + 1) << 5;
            #pragma unroll
            for (int i = 0; i < 4; i++) {
                sA[i] = *(const float4*)(A + (brow + fr[i])*(long)lda + k0 + fkc[i]);
                sB[i] = *(const float4*)(B + (bcol + fr[i])*(long)ldb + k0 + fkc[i]);
            }
        }

        #pragma unroll
        for (int kb = 0; kb < 4; kb++) {
            const int kk = kb*8 + tig;
            uint32_t af[2][4];
            #pragma unroll
            for (int ia = 0; ia < 2; ia++) {
                int m0 = warp_m*32 + ia*16 + gid;
                int x  = (m0 & 7) << 2;
                af[ia][0] = As[m0*32     + (kk     ^ x)];
                af[ia][1] = As[(m0+8)*32 + (kk     ^ x)];
                af[ia][2] = As[m0*32     + ((kk+4) ^ x)];
                af[ia][3] = As[(m0+8)*32 + ((kk+4) ^ x)];
            }
            uint32_t bf[8][2];
            #pragma unroll
            for (int nb = 0; nb < 8; nb++) {
                int n = warp_n*64 + nb*8 + gid;
                int x = (n & 7) << 2;
                bf[nb][0] = Bs[n*32 + (kk     ^ x)];
                bf[nb][1] = Bs[n*32 + ((kk+4) ^ x)];
            }
            #pragma unroll
            for (int im = 0; im < 2; im++)
                #pragma unroll
                for (int in_ = 0; in_ < 8; in_++) {
                    asm volatile(
                        "mma.sync.aligned.m16n8k8.row.col.f32.tf32.tf32.f32 "
                        "{%0,%1,%2,%3}, {%4,%5,%6,%7}, {%8,%9}, {%0,%1,%2,%3};"
                        : "+f"(c[im][in_][0]), "+f"(c[im][in_][1]),
                          "+f"(c[im][in_][2]), "+f"(c[im][in_][3])
                        : "r"(af[im][0]), "r"(af[im][1]), "r"(af[im][2]), "r"(af[im][3]),
                          "r"(bf[in_][0]), "r"(bf[in_][1]));
                }
        }
        __syncthreads();
    }

    #pragma unroll
    for (int im = 0; im < 2; im++) {
        long r0 = brow + warp_m*32 + im*16 + gid;
        #pragma unroll
        for (int in_ = 0; in_ < 8; in_++) {
            long cb = bcol + warp_n*64 + in_*8 + tig*2;
            #pragma unroll
            for (int half = 0; half < 2; half++) {
                long row = r0 + half*8;
                float v0 = c[im][in_][half*2 + 0];
                float v1 = c[im][in_][half*2 + 1];
                if (bias) { v0 += bias[cb]; v1 += bias[cb + 1]; }
                if (relu) { v0 = fmaxf(v0, 0.f); v1 = fmaxf(v1, 0.f); }
                *(float2*)(C + row*(long)ldc + cb) = make_float2(v0, v1);
            }
        }
    }
}

// ================= persistent Phase B =================
__device__ __forceinline__ void grid_sync()
{
    __syncthreads();
    if (threadIdx.x == 0) {
        unsigned gen = g_gen;
        __threadfence();
        if (atomicAdd(&g_cnt, 1u) == PCTA - 1u) {
            g_cnt = 0u;
            __threadfence();
            g_gen = gen + 1u;
        } else {
            while (g_gen == gen) { __nanosleep(64); }
            __threadfence();
        }
    }
    __syncthreads();
}

// one 64x128 output tile; MODE 0: plain A; MODE 1: A = [z | a] fused loader (K=288)
template<int MODE>
__device__ __forceinline__ void dev_tile64(
    const float* __restrict__ A, int lda,
    const float* __restrict__ B, int ldb,
    float* __restrict__ C, int ldc,
    const float* __restrict__ bias,
    int K, int brow, int bcol,
    const float* __restrict__ zS, const float* __restrict__ zpe,
    const float* __restrict__ zeps, const float* __restrict__ zact,
    float* __restrict__ zfeat, bool pz,
    uint32_t* As, uint32_t* Bs)
{
    const int tid = threadIdx.x;
    const int wid = tid >> 5, lane = tid & 31;
    const int warp_m = wid & 1;
    const int warp_n = wid >> 1;
    const int gid = lane >> 2, tig = lane & 3;
    const int nch = K >> 5;

    float c[2][4][4];
    #pragma unroll
    for (int im = 0; im < 2; im++)
        #pragma unroll
        for (int in_ = 0; in_ < 4; in_++)
            #pragma unroll
            for (int j = 0; j < 4; j++) c[im][in_][j] = 0.0f;

    int fr[2], fkc[2];
    #pragma unroll
    for (int i = 0; i < 2; i++) {
        int lin = i*256 + tid;
        fr[i]  = lin >> 3;
        fkc[i] = (lin & 7) << 2;
    }
    int gr[4], gkc[4];
    #pragma unroll
    for (int i = 0; i < 4; i++) {
        int lin = i*256 + tid;
        gr[i]  = lin >> 3;
        gkc[i] = (lin & 7) << 2;
    }

    float4 sA[2], sB[4];

    #define PB_LOAD(k0)                                                            \
    do {                                                                           \
        _Pragma("unroll")                                                          \
        for (int i = 0; i < 2; i++) {                                              \
            if (MODE == 0) {                                                       \
                sA[i] = *(const float4*)(A + (long)(brow + fr[i])*lda + (k0) + fkc[i]); \
            } else {                                                               \
                int b = brow + fr[i];                                              \
                int j = (k0) + fkc[i];                                             \
                if (j < 256) {                                                     \
                    float4 qm = *(const float4*)(zS + (long)b*SN + j);             \
                    float4 p1 = *(const float4*)(zpe + (long)b*512 + j);           \
                    float4 ql = *(const float4*)(zS + (long)b*SN + 256 + j);       \
                    float4 p2 = *(const float4*)(zpe + (long)b*512 + 256 + j);     \
                    float4 e  = *(const float4*)(zeps + (long)b*256 + j);          \
                    float4 z;                                                      \
                    z.x = (qm.x + p1.x) + e.x * expf(ql.x + p2.x);                 \
                    z.y = (qm.y + p1.y) + e.y * expf(ql.y + p2.y);                 \
                    z.z = (qm.z + p1.z) + e.z * expf(ql.z + p2.z);                 \
                    z.w = (qm.w + p1.w) + e.w * expf(ql.w + p2.w);                 \
                    if (pz) *(float4*)(zfeat + (long)b*FEATD + DETD + j) = z;      \
                    sA[i] = z;                                                     \
                } else {                                                           \
                    sA[i] = *(const float4*)(zact + (long)b*ACTD + (j - 256));     \
                }                                                                  \
            }                                                                      \
        }                                                                          \
        _Pragma("unroll")                                                          \
        for (int i = 0; i < 4; i++)                                                \
            sB[i] = *(const float4*)(B + (long)(bcol + gr[i])*ldb + (k0) + gkc[i]); \
    } while (0)

    PB_LOAD(0);

    for (int cch = 0; cch < nch; cch++) {
        #pragma unroll
        for (int i = 0; i < 2; i++) {
            uint4 t;
            t.x = f2tf(sA[i].x); t.y = f2tf(sA[i].y);
            t.z = f2tf(sA[i].z); t.w = f2tf(sA[i].w);
            *(uint4*)&As[swz(fr[i], fkc[i])] = t;
        }
        #pragma unroll
        for (int i = 0; i < 4; i++) {
            uint4 t;
            t.x = f2tf(sB[i].x); t.y = f2tf(sB[i].y);
            t.z = f2tf(sB[i].z); t.w = f2tf(sB[i].w);
            *(uint4*)&Bs[swz(gr[i], gkc[i])] = t;
        }
        __syncthreads();

        if (cch + 1 < nch) {
            int k0 = (cch + 1) << 5;
            PB_LOAD(k0);
        }

        #pragma unroll
        for (int kb = 0; kb < 4; kb++) {
            const int kk = kb*8 + tig;
            uint32_t af[2][4];
            #pragma unroll
            for (int ia = 0; ia < 2; ia++) {
                int m0 = warp_m*32 + ia*16 + gid;
                int x  = (m0 & 7) << 2;
                af[ia][0] = As[m0*32     + (kk     ^ x)];
                af[ia][1] = As[(m0+8)*32 + (kk     ^ x)];
                af[ia][2] = As[m0*32     + ((kk+4) ^ x)];
                af[ia][3] = As[(m0+8)*32 + ((kk+4) ^ x)];
            }
            uint32_t bf[4][2];
            #pragma unroll
            for (int nb = 0; nb < 4; nb++) {
                int n = warp_n*32 + nb*8 + gid;
                int x = (n & 7) << 2;
                bf[nb][0] = Bs[n*32 + (kk     ^ x)];
                bf[nb][1] = Bs[n*32 + ((kk+4) ^ x)];
            }
            #pragma unroll
            for (int im = 0; im < 2; im++)
                #pragma unroll
                for (int in_ = 0; in_ < 4; in_++) {
                    asm volatile(
                        "mma.sync.aligned.m16n8k8.row.col.f32.tf32.tf32.f32 "
                        "{%0,%1,%2,%3}, {%4,%5,%6,%7}, {%8,%9}, {%0,%1,%2,%3};"
                        : "+f"(c[im][in_][0]), "+f"(c[im][in_][1]),
                          "+f"(c[im][in_][2]), "+f"(c[im][in_][3])
                        : "r"(af[im][0]), "r"(af[im][1]), "r"(af[im][2]), "r"(af[im][3]),
                          "r"(bf[in_][0]), "r"(bf[in_][1]));
                }
        }
        __syncthreads();
    }
    #undef PB_LOAD

    #pragma unroll
    for (int im = 0; im < 2; im++) {
        long r0 = brow + warp_m*32 + im*16 + gid;
        #pragma unroll
        for (int in_ = 0; in_ < 4; in_++) {
            long cb = bcol + warp_n*32 + in_*8 + tig*2;
            #pragma unroll
            for (int half = 0; half < 2; half++) {
                long row = r0 + half*8;
                float v0 = c[im][in_][half*2 + 0];
                float v1 = c[im][in_][half*2 + 1];
                if (bias) { v0 += bias[cb]; v1 += bias[cb + 1]; }
                *(float2*)(C + row*(long)ldc + cb) = make_float2(v0, v1);
            }
        }
    }
}

__global__ void __launch_bounds__(256) phaseB_k(
    const float* __restrict__ eps,
    const float* __restrict__ actions,
    const unsigned char* __restrict__ dones,
    const float* __restrict__ gru_wih,
    const float* __restrict__ gru_bih)
{
    __shared__ __align__(16) uint32_t As[64*32];
    __shared__ __align__(16) uint32_t Bs[128*32];
    const int bid = blockIdx.x;

    for (int t = 0; t < TS; t++) {
        float* S_t = g_S_all + (size_t)t*BB*SN;

        // task A: S_t = h @ [post_w_h | whh^T] + bh2 (112 tiles, 1/CTA)
        {
            int tm = bid / 28, tn = bid % 28;
            dev_tile64<0>(g_h, DETD, g_Wh2T, DETD, S_t, SN, g_bh2,
                          DETD, tm*64, tn*128,
                          nullptr, nullptr, nullptr, nullptr, nullptr, false,
                          As, Bs);
        }
        grid_sync();

        // task B: G = [z | a_t] @ wih^T + bih (96 tiles)
        if (bid < 96) {
            int tm = bid / 24, tn = bid % 24;
            dev_tile64<1>(nullptr, 0, gru_wih, STOD+ACTD, g_G, 3*DETD, gru_bih,
                          STOD+ACTD, tm*64, tn*128,
                          S_t, g_post_emb + (size_t)t*BB*512,
                          eps + (size_t)t*BB*STOD,
                          actions + (size_t)t*BB*ACTD,
                          g_feat + (size_t)t*BB*FEATD, tn == 0,
                          As, Bs);
        }
        grid_sync();

        // task C: GRU update
        for (int idx = bid*256 + threadIdx.x; idx < BB*DETD; idx += PCTA*256) {
            int b = idx >> 10, n = idx & 1023;
            const float* Gr = g_G + (long)b*3*DETD;
            const float* Sr = S_t + (long)b*SN;
            float ir = Gr[n], iz = Gr[1024 + n], inn = Gr[2048 + n];
            float hr = Sr[512 + n], hz = Sr[1536 + n], hn = Sr[2560 + n];
            float r  = 1.0f / (1.0f + expf(-(ir + hr)));
            float u  = 1.0f / (1.0f + expf(-(iz + hz)));
            float nn = tanhf(inn + r * hn);
            float hp = g_h[idx];
            float hnew = (1.0f - u) * nn + u * hp;
            g_feat[((size_t)t*BB + b)*FEATD + n] = hnew;
            float hm = dones[t*BB + b] ? 0.0f : hnew;
            g_h[idx] = hm;
            if (t + 1 < TS) g_hin[(size_t)(t+1)*BB*DETD + idx] = hm;
        }
        grid_sync();
    }
}

// ---------------- weight prep ----------------
__global__ void transpose_k(float* __restrict__ dst, const float* __restrict__ src, int K, int N)
{
    long idx = (long)blockIdx.x * blockDim.x + threadIdx.x;
    if (idx >= (long)K * N) return;
    int n = (int)(idx / K), k = (int)(idx % K);
    dst[idx] = src[(long)k * N + n];
}

__global__ void prep_wh2T_k(const float* __restrict__ post_w,
                            const float* __restrict__ gru_whh, const float* __restrict__ gru_bhh)
{
    long idx = (long)blockIdx.x * blockDim.x + threadIdx.x;
    if (idx < (long)SN * DETD) {
        int n = (int)(idx >> 10), k = (int)(idx & 1023);
        g_Wh2T[idx] = (n < 512) ? post_w[k*512 + n]
                                : gru_whh[(long)(n - 512)*DETD + k];
    }
    if (idx < SN) {
        int n = (int)idx;
        g_bh2[n] = (n < 512) ? 0.0f : gru_bhh[n - 512];
    }
}

__global__ void prep_priorT_k(const float* __restrict__ prior_w)
{
    long idx = (long)blockIdx.x * blockDim.x + threadIdx.x;
    if (idx >= (long)512 * DETD) return;
    int n = (int)(idx >> 10), k = (int)(idx & 1023);
    g_priorT[idx] = prior_w[k*512 + n];
}

__global__ void prep_w1fT_k(const float* __restrict__ dec_w1, const float* __restrict__ dec_b1,
                            const float* __restrict__ rew_w1, const float* __restrict__ rew_b1)
{
    long idx = (long)blockIdx.x * blockDim.x + threadIdx.x;
    if (idx < (long)2048 * FEATD) {
        int n = (int)(idx / FEATD), k = (int)(idx % FEATD);
        g_W1fT[idx] = (n < 1024) ? dec_w1[(long)k*1024 + n] : rew_w1[(long)k*1024 + (n - 1024)];
    }
    if (idx < 2048) {
        int n = (int)idx;
        g_b1f[n] = (n < 1024) ? dec_b1[n] : rew_b1[n - 1024];
    }
}

__global__ void prep_postEmbT_k(const float* __restrict__ post_w)
{
    long idx = (long)blockIdx.x * blockDim.x + threadIdx.x;
    if (idx >= (long)2*STOD*EMBD) return;
    int n = (int)(idx >> 10), k = (int)(idx & 1023);
    g_postEmbT[idx] = post_w[(long)(1024 + k)*512 + n];
}

// ---------------- batched loss kernels ----------------
__global__ void klbatch_k()
{
    int row = blockIdx.x, j = threadIdx.x;
    const float* Sr = g_S_all + (size_t)row*SN;
    const float* pe = g_post_emb + (long)row*512;
    const float* pr = g_prior + (long)row*512;
    float pm = pr[j], pl = pr[256 + j];
    float qm = Sr[j]       + pe[j];
    float ql = Sr[256 + j] + pe[256 + j];
    float vq = expf(2.0f*ql), vp = expf(2.0f*pl);
    float d  = qm - pm;
    float kl = pl - ql + (vq + d*d) / (vp + 1e-8f) - 1.0f;

    __shared__ float red[STOD];
    red[j] = kl; __syncthreads();
    for (int s = STOD/2; s > 0; s >>= 1) {
        if (j < s) red[j] += red[j + s];
        __syncthreads();
    }
    if (j == 0) g_kl[row] = 0.5f * red[0];
}

__global__ void recon_k(const float* __restrict__ obs)
{
    int r = blockIdx.x, t = threadIdx.x;
    const float* p = g_pred + (long)r*OBSD;
    const float* o = obs + ((long)r + BB)*OBSD;
    float s = 0.0f;
    for (int i = t; i < OBSD; i += 128) { float d = p[i] - o[i]; s += d*d; }
    __shared__ float red[128];
    red[t] = s; __syncthreads();
    for (int st = 64; st > 0; st >>= 1) {
        if (t < st) red[t] += red[t + st];
        __syncthreads();
    }
    if (t == 0) g_recon[r] = red[0] / (float)OBSD;
}

__global__ void rew_k(const float* __restrict__ rewards,
                      const float* __restrict__ rew_w2, const float* __restrict__ rew_b2)
{
    int r = blockIdx.x, t = threadIdx.x;
    const float* hrow = g_H1 + (long)r*2048 + 1024;
    float s = 0.0f;
    for (int i = t; i < 1024; i += 256) s += hrow[i] * rew_w2[i];
    __shared__ float red[256];
    red[t] = s; __syncthreads();
    for (int st = 128; st > 0; st >>= 1) {
        if (t < st) red[t] += red[t + st];
        __syncthreads();
    }
    if (t == 0) {
        float pred = red[0] + rew_b2[0];
        float d = pred - rewards[r];
        g_rewl[r] = d*d;
    }
}

__global__ void final_k(float* __restrict__ out)
{
    int t = threadIdx.x;
    float a = 0, b = 0, c = 0;
    for (int i = t; i < RR; i += 256) { a += g_recon[i]; b += g_rewl[i]; c += g_kl[i]; }
    __shared__ float sa[256], sb[256], sc[256];
    sa[t] = a; sb[t] = b; sc[t] = c; __syncthreads();
    for (int s = 128; s > 0; s >>= 1) {
        if (t < s) { sa[t] += sa[t+s]; sb[t] += sb[t+s]; sc[t] += sc[t+s]; }
        __syncthreads();
    }
    if (t == 0) {
        float recon = sa[0] / (float)RR;
        float rew   = sb[0] / (float)RR;
        float kl    = sc[0] / (float)RR;
        out[0] = recon + rew + kl;
        out[1] = recon;
        out[2] = rew;
        out[3] = kl;
    }
}

// ---------------- host ----------------
static inline void run128(const float* A, int lda, const float* B, int ldb,
                          float* C, int ldc, const float* bias,
                          int M, int N, int K, int relu)
{
    dim3 grid(N/128, M/128);
    mma_gemm128<<<grid, 256>>>(A, lda, B, ldb, C, ldc, bias, K, relu);
}

extern "C" void kernel_launch(void* const* d_in, const int* in_sizes, int n_in,
                              void* d_out, int out_size)
{
    const float* obs     = (const float*)d_in[0];
    const float* actions = (const float*)d_in[1];
    const float* rewards = (const float*)d_in[2];
    const unsigned char* dones = (const unsigned char*)d_in[3];
    const float* eps     = (const float*)d_in[4];
    const float* enc_w1  = (const float*)d_in[5];
    const float* enc_b1  = (const float*)d_in[6];
    const float* enc_w2  = (const float*)d_in[7];
    const float* enc_b2  = (const float*)d_in[8];
    const float* gru_wih = (const float*)d_in[9];
    const float* gru_whh = (const float*)d_in[10];
    const float* gru_bih = (const float*)d_in[11];
    const float* gru_bhh = (const float*)d_in[12];
    const float* prior_w = (const float*)d_in[13];
    const float* prior_b = (const float*)d_in[14];
    const float* post_w  = (const float*)d_in[15];
    const float* post_b  = (const float*)d_in[16];
    const float* dec_w1  = (const float*)d_in[17];
    const float* dec_b1  = (const float*)d_in[18];
    const float* dec_w2  = (const float*)d_in[19];
    const float* dec_b2  = (const float*)d_in[20];
    const float* rew_w1  = (const float*)d_in[21];
    const float* rew_b1  = (const float*)d_in[22];
    const float* rew_w2  = (const float*)d_in[23];
    const float* rew_b2  = (const float*)d_in[24];
    float* out = (float*)d_out;

    #define SYM(p, s) float* p; cudaGetSymbolAddress((void**)&p, s)
    SYM(p_embh, g_embh);     SYM(p_emb, g_emb);       SYM(p_post_emb, g_post_emb);
    SYM(p_feat, g_feat);     SYM(p_H1, g_H1);         SYM(p_pred, g_pred);
    SYM(p_hin, g_hin);       SYM(p_h, g_h);           SYM(p_prior, g_prior);
    SYM(p_priorT, g_priorT); SYM(p_W1fT, g_W1fT);     SYM(p_b1f, g_b1f);
    SYM(p_encw1T, g_encw1T); SYM(p_encw2T, g_encw2T);
    SYM(p_postEmbT, g_postEmbT); SYM(p_decw2T, g_decw2T);
    #undef SYM
    {
        void* a; cudaGetSymbolAddress(&a, g_cnt);
        cudaMemsetAsync(a, 0, sizeof(unsigned));
        void* b; cudaGetSymbolAddress(&b, g_gen);
        cudaMemsetAsync(b, 0, sizeof(unsigned));
    }

    cudaMemsetAsync(p_h, 0, (size_t)BB*DETD*sizeof(float));
    cudaMemsetAsync(p_hin, 0, (size_t)BB*DETD*sizeof(float));  // h_in[0] = 0

    // ---- weight prep ----
    {
        long n;
        n = (long)EMBD*OBSD;
        transpose_k<<<(unsigned)((n+255)/256), 256>>>(p_encw1T, enc_w1, OBSD, EMBD);
        n = (long)EMBD*EMBD;
        transpose_k<<<(unsigned)((n+255)/256), 256>>>(p_encw2T, enc_w2, EMBD, EMBD);
        n = (long)OBSD*EMBD;
        transpose_k<<<(unsigned)((n+255)/256), 256>>>(p_decw2T, dec_w2, EMBD, OBSD);
        n = (long)2*STOD*EMBD;
        prep_postEmbT_k<<<(unsigned)((n+255)/256), 256>>>(post_w);
        n = (long)SN*DETD;
        prep_wh2T_k<<<(unsigned)((n+255)/256), 256>>>(post_w, gru_whh, gru_bhh);
        n = (long)512*DETD;
        prep_priorT_k<<<(unsigned)((n+255)/256), 256>>>(prior_w);
        n = (long)2048*FEATD;
        prep_w1fT_k<<<(unsigned)((n+255)/256), 256>>>(dec_w1, dec_b1, rew_w1, rew_b1);
    }

    // ---- Phase A: time-batched precompute ----
    run128(obs, OBSD, p_encw1T, OBSD, p_embh, EMBD, enc_b1, RR, EMBD, OBSD, 1);
    run128(p_embh, EMBD, p_encw2T, EMBD, p_emb, EMBD, enc_b2, RR, EMBD, EMBD, 1);
    run128(p_emb, EMBD, p_postEmbT, EMBD, p_post_emb, 2*STOD, post_b, RR, 2*STOD, EMBD, 0);

    // ---- Phase B: persistent recurrence ----
    phaseB_k<<<PCTA, 256>>>(eps, actions, dones, gru_wih, gru_bih);

    // ---- Phase C: batched prior + KL + decoder / reward / losses ----
    run128(p_hin, DETD, p_priorT, DETD, p_prior, 512, prior_b, RR, 512, DETD, 0);
    klbatch_k<<<RR, STOD>>>();
    run128(p_feat, FEATD, p_W1fT, FEATD, p_H1, 2048, p_b1f, RR, 2048, FEATD, 1);
    run128(p_H1, 2048, p_decw2T, EMBD, p_pred, OBSD, dec_b2, RR, OBSD, EMBD, 0);
    recon_k<<<RR, 128>>>(obs);
    rew_k<<<RR, 256>>>(rewards, rew_w2, rew_b2);
    final_k<<<1, 256>>>(out);

    (void)in_sizes; (void)n_in; (void)out_size;
}

// round 10
// speedup vs baseline: 1.3917x; 1.3917x over previous
#include <cuda_runtime.h>
#include <math.h>
#include <stdint.h>

// ---------------- problem constants ----------------
#define TS   63
#define BB   256
#define OBSD 512
#define ACTD 32
#define EMBD 1024
#define DETD 1024
#define STOD 256
#define RR   (TS*BB)
#define FEATD (DETD+STOD)   // 1280
#define SN   4096           // S width: [prior 512 | post 512 | gh 3072]

// ---------------- device scratch ----------------
__device__ float g_obsr[RR*OBSD];           // RNA-rounded obs[:-1]
__device__ float g_embh[RR*EMBD];
__device__ float g_emb [RR*EMBD];
__device__ float g_post_emb[RR*512];
__device__ float g_feat[RR*FEATD];          // [h | z], tf32-rounded
__device__ float g_H1  [RR*2048];
__device__ float g_pred[RR*OBSD];
__device__ float g_S_all[(size_t)RR*SN];
__device__ float g_h[BB*DETD];
__device__ float g_kl[RR];
__device__ float g_recon[RR];
__device__ float g_rewl[RR];
// weights (RNA-rounded), pre-transposed to [N,K]
__device__ float g_WhT[SN*DETD];            // [prior | post_h | whh^T]
__device__ float g_bh[SN];
__device__ float g_wihR[3*DETD*(STOD+ACTD)];
__device__ float g_encw1T[EMBD*OBSD];
__device__ float g_encw2T[EMBD*EMBD];
__device__ float g_postEmbT[512*EMBD];
__device__ float g_decw2T[OBSD*EMBD];
__device__ float g_W1fT[2048*FEATD];
__device__ float g_b1f[2048];

__device__ __forceinline__ float f2tf(float f) {
    uint32_t r;
    asm("cvt.rna.tf32.f32 %0, %1;" : "=r"(r) : "f"(f));
    return __uint_as_float(r);
}
__device__ __forceinline__ int swz(int r, int k) {
    return r*32 + (k ^ ((r & 7) << 2));
}
__device__ __forceinline__ void cp16(uint32_t saddr, const void* g) {
    asm volatile("cp.async.cg.shared.global [%0], [%1], 16;" :: "r"(saddr), "l"(g));
}
__device__ __forceinline__ void cp_commit() {
    asm volatile("cp.async.commit_group;" ::: "memory");
}
template<int N> __device__ __forceinline__ void cp_wait() {
    asm volatile("cp.async.wait_group %0;" :: "n"(N) : "memory");
}

// ================= cp.async double-buffered tf32 GEMM =================
// All operands are PRE-ROUNDED to tf32 values (stored as f32), so the MMA's
// HW truncation is exact. rndout: round outputs consumed by downstream GEMMs.
template<int BM>
__global__ void __launch_bounds__(256) ca_gemm(
    const float* __restrict__ A, int lda,
    const float* __restrict__ B, int ldb,
    float* __restrict__ C, int ldc,
    const float* __restrict__ bias, int K, int relu, int rndout)
{
    extern __shared__ float smem[];
    float* As = smem;                 // 2 * BM*32
    float* Bs = smem + 2*BM*32;       // 2 * 128*32

    const int tid = threadIdx.x;
    const int wid = tid >> 5, lane = tid & 31;
    constexpr int WM   = BM/32;
    constexpr int WN   = 8/WM;
    constexpr int NCOL = 128/WN;
    constexpr int NAT  = NCOL/8;
    const int warp_m = wid % WM;
    const int warp_n = wid / WM;
    const int gid = lane >> 2, tig = lane & 3;
    const long brow = (long)blockIdx.y * BM;
    const long bcol = (long)blockIdx.x * 128;
    const int nch = K >> 5;

    const uint32_t as_u = (uint32_t)__cvta_generic_to_shared(As);
    const uint32_t bs_u = (uint32_t)__cvta_generic_to_shared(Bs);

    float c[2][NAT][4];
    #pragma unroll
    for (int im = 0; im < 2; im++)
        #pragma unroll
        for (int in_ = 0; in_ < NAT; in_++)
            #pragma unroll
            for (int j = 0; j < 4; j++) c[im][in_][j] = 0.0f;

    constexpr int NA = BM/32;
    int fr[NA], fkc[NA];
    #pragma unroll
    for (int i = 0; i < NA; i++) {
        int lin = i*256 + tid;
        fr[i]  = lin >> 3;
        fkc[i] = (lin & 7) << 2;
    }
    int gr[4], gkc[4];
    #pragma unroll
    for (int i = 0; i < 4; i++) {
        int lin = i*256 + tid;
        gr[i]  = lin >> 3;
        gkc[i] = (lin & 7) << 2;
    }

    #define CA_ISSUE(cc)                                                           \
    do {                                                                           \
        int k0 = (cc) << 5; int buf = (cc) & 1;                                    \
        _Pragma("unroll")                                                          \
        for (int i = 0; i < NA; i++)                                               \
            cp16(as_u + (uint32_t)(buf*BM*32 + swz(fr[i], fkc[i]))*4,              \
                 A + (brow + fr[i])*(long)lda + k0 + fkc[i]);                      \
        _Pragma("unroll")                                                          \
        for (int i = 0; i < 4; i++)                                                \
            cp16(bs_u + (uint32_t)(buf*128*32 + swz(gr[i], gkc[i]))*4,             \
                 B + (bcol + gr[i])*(long)ldb + k0 + gkc[i]);                      \
        cp_commit();                                                               \
    } while (0)

    CA_ISSUE(0);

    for (int cch = 0; cch < nch; cch++) {
        if (cch + 1 < nch) { CA_ISSUE(cch + 1); cp_wait<1>(); }
        else               { cp_wait<0>(); }
        __syncthreads();

        const uint32_t* Ap = (const uint32_t*)(As + (cch & 1)*BM*32);
        const uint32_t* Bp = (const uint32_t*)(Bs + (cch & 1)*128*32);

        #pragma unroll
        for (int kb = 0; kb < 4; kb++) {
            const int kk = kb*8 + tig;
            uint32_t af[2][4];
            #pragma unroll
            for (int ia = 0; ia < 2; ia++) {
                int m0 = warp_m*32 + ia*16 + gid;
                int x  = (m0 & 7) << 2;
                af[ia][0] = Ap[m0*32     + (kk     ^ x)];
                af[ia][1] = Ap[(m0+8)*32 + (kk     ^ x)];
                af[ia][2] = Ap[m0*32     + ((kk+4) ^ x)];
                af[ia][3] = Ap[(m0+8)*32 + ((kk+4) ^ x)];
            }
            uint32_t bf[NAT][2];
            #pragma unroll
            for (int nb = 0; nb < NAT; nb++) {
                int n = warp_n*NCOL + nb*8 + gid;
                int x = (n & 7) << 2;
                bf[nb][0] = Bp[n*32 + (kk     ^ x)];
                bf[nb][1] = Bp[n*32 + ((kk+4) ^ x)];
            }
            #pragma unroll
            for (int im = 0; im < 2; im++)
                #pragma unroll
                for (int in_ = 0; in_ < NAT; in_++) {
                    asm volatile(
                        "mma.sync.aligned.m16n8k8.row.col.f32.tf32.tf32.f32 "
                        "{%0,%1,%2,%3}, {%4,%5,%6,%7}, {%8,%9}, {%0,%1,%2,%3};"
                        : "+f"(c[im][in_][0]), "+f"(c[im][in_][1]),
                          "+f"(c[im][in_][2]), "+f"(c[im][in_][3])
                        : "r"(af[im][0]), "r"(af[im][1]), "r"(af[im][2]), "r"(af[im][3]),
                          "r"(bf[in_][0]), "r"(bf[in_][1]));
                }
        }
        __syncthreads();
    }
    #undef CA_ISSUE

    #pragma unroll
    for (int im = 0; im < 2; im++) {
        long r0 = brow + warp_m*32 + im*16 + gid;
        #pragma unroll
        for (int in_ = 0; in_ < NAT; in_++) {
            long cb = bcol + warp_n*NCOL + in_*8 + tig*2;
            #pragma unroll
            for (int half = 0; half < 2; half++) {
                long row = r0 + half*8;
                float v0 = c[im][in_][half*2 + 0];
                float v1 = c[im][in_][half*2 + 1];
                if (bias) { v0 += bias[cb]; v1 += bias[cb + 1]; }
                if (relu) { v0 = fmaxf(v0, 0.f); v1 = fmaxf(v1, 0.f); }
                if (rndout) { v0 = f2tf(v0); v1 = f2tf(v1); }
                *(float2*)(C + row*(long)ldc + cb) = make_float2(v0, v1);
            }
        }
    }
}

// ================= fused Gz + GRU kernel =================
// grid (nb=8, tm=8). Tile: 32 rows x 384 cols (3 gates x 128 n).
// A = [z | a] (z computed from S/post_emb/eps), K=288, rounded at staging.
__global__ void __launch_bounds__(256) gzgru_k(
    const float* __restrict__ S,          // [BB, 4096]
    const float* __restrict__ pe,         // [BB, 512]
    const float* __restrict__ epst,       // [BB, 256]
    const float* __restrict__ act,        // [BB, 32]
    const float* __restrict__ wih,        // [3072, 288] rounded
    const float* __restrict__ bih,        // [3072]
    const unsigned char* __restrict__ dn, // [BB]
    float* __restrict__ feat_t)           // [BB, FEATD]
{
    extern __shared__ float smem[];
    float* As  = smem;                 // 32*32 = 1024
    float* Bs  = smem + 1024;          // 2 * 384*32 = 24576
    float* Gsm = smem;                 // alias, used post-GEMM

    const int tid = threadIdx.x;
    const int wid = tid >> 5, lane = tid & 31;
    const int gid = lane >> 2, tig = lane & 3;
    const int nb = blockIdx.x;
    const int brow = blockIdx.y * 32;
    const int nch = 9;                 // K = 288

    const uint32_t bs_u = (uint32_t)__cvta_generic_to_shared(Bs);

    float c[2][6][4];
    #pragma unroll
    for (int im = 0; im < 2; im++)
        #pragma unroll
        for (int in_ = 0; in_ < 6; in_++)
            #pragma unroll
            for (int j = 0; j < 4; j++) c[im][in_][j] = 0.0f;

    const int fr = tid >> 3, fkc = (tid & 7) << 2;
    int gr[12], gkc[12];
    #pragma unroll
    for (int i = 0; i < 12; i++) {
        int lin = i*256 + tid;
        gr[i]  = lin >> 3;
        gkc[i] = (lin & 7) << 2;
    }

    #define GZ_ISSUE_B(cc)                                                         \
    do {                                                                           \
        int k0 = (cc) << 5; int buf = (cc) & 1;                                    \
        _Pragma("unroll")                                                          \
        for (int i = 0; i < 12; i++) {                                             \
            int grow = (gr[i] >> 7)*1024 + nb*128 + (gr[i] & 127);                 \
            cp16(bs_u + (uint32_t)(buf*12288 + swz(gr[i], gkc[i]))*4,              \
                 wih + (long)grow*288 + k0 + gkc[i]);                              \
        }                                                                          \
        cp_commit();                                                               \
    } while (0)

    float4 sA;
    #define GZ_LOAD_A(cc)                                                          \
    do {                                                                           \
        int j = ((cc) << 5) + fkc;                                                 \
        int b = brow + fr;                                                         \
        if (j < 256) {                                                             \
            float4 qm = *(const float4*)(S + (long)b*SN + 512 + j);                \
            float4 p1 = *(const float4*)(pe + (long)b*512 + j);                    \
            float4 ql = *(const float4*)(S + (long)b*SN + 768 + j);                \
            float4 p2 = *(const float4*)(pe + (long)b*512 + 256 + j);              \
            float4 e  = *(const float4*)(epst + (long)b*256 + j);                  \
            float4 z;                                                              \
            z.x = f2tf((qm.x + p1.x) + e.x * expf(ql.x + p2.x));                   \
            z.y = f2tf((qm.y + p1.y) + e.y * expf(ql.y + p2.y));                   \
            z.z = f2tf((qm.z + p1.z) + e.z * expf(ql.z + p2.z));                   \
            z.w = f2tf((qm.w + p1.w) + e.w * expf(ql.w + p2.w));                   \
            if (nb == 0) *(float4*)(feat_t + (long)b*FEATD + DETD + j) = z;        \
            sA = z;                                                                \
        } else {                                                                   \
            float4 a = *(const float4*)(act + (long)b*ACTD + (j - 256));           \
            a.x = f2tf(a.x); a.y = f2tf(a.y); a.z = f2tf(a.z); a.w = f2tf(a.w);    \
            sA = a;                                                                \
        }                                                                          \
    } while (0)

    GZ_ISSUE_B(0);
    GZ_LOAD_A(0);

    for (int cch = 0; cch < nch; cch++) {
        __syncthreads();
        *(float4*)&As[swz(fr, fkc)] = sA;
        if (cch + 1 < nch) { GZ_ISSUE_B(cch + 1); cp_wait<1>(); }
        else               { cp_wait<0>(); }
        __syncthreads();
        if (cch + 1 < nch) GZ_LOAD_A(cch + 1);

        const uint32_t* Ap = (const uint32_t*)As;
        const uint32_t* Bp = (const uint32_t*)(Bs + (cch & 1)*12288);

        #pragma unroll
        for (int kb = 0; kb < 4; kb++) {
            const int kk = kb*8 + tig;
            uint32_t af[2][4];
            #pragma unroll
            for (int ia = 0; ia < 2; ia++) {
                int m0 = ia*16 + gid;
                int x  = (m0 & 7) << 2;
                af[ia][0] = Ap[m0*32     + (kk     ^ x)];
                af[ia][1] = Ap[(m0+8)*32 + (kk     ^ x)];
                af[ia][2] = Ap[m0*32     + ((kk+4) ^ x)];
                af[ia][3] = Ap[(m0+8)*32 + ((kk+4) ^ x)];
            }
            uint32_t bf[6][2];
            #pragma unroll
            for (int nbi = 0; nbi < 6; nbi++) {
                int n = wid*48 + nbi*8 + gid;
                int x = (n & 7) << 2;
                bf[nbi][0] = Bp[n*32 + (kk     ^ x)];
                bf[nbi][1] = Bp[n*32 + ((kk+4) ^ x)];
            }
            #pragma unroll
            for (int im = 0; im < 2; im++)
                #pragma unroll
                for (int in_ = 0; in_ < 6; in_++) {
                    asm volatile(
                        "mma.sync.aligned.m16n8k8.row.col.f32.tf32.tf32.f32 "
                        "{%0,%1,%2,%3}, {%4,%5,%6,%7}, {%8,%9}, {%0,%1,%2,%3};"
                        : "+f"(c[im][in_][0]), "+f"(c[im][in_][1]),
                          "+f"(c[im][in_][2]), "+f"(c[im][in_][3])
                        : "r"(af[im][0]), "r"(af[im][1]), "r"(af[im][2]), "r"(af[im][3]),
                          "r"(bf[in_][0]), "r"(bf[in_][1]));
                }
        }
    }
    __syncthreads();

    // stage G (32 x 384) into smem
    #pragma unroll
    for (int im = 0; im < 2; im++) {
        int r0 = im*16 + gid;
        #pragma unroll
        for (int in_ = 0; in_ < 6; in_++) {
            int cb = wid*48 + in_*8 + tig*2;
            #pragma unroll
            for (int half = 0; half < 2; half++) {
                int row = r0 + half*8;
                Gsm[row*384 + cb]     = c[im][in_][half*2 + 0];
                Gsm[row*384 + cb + 1] = c[im][in_][half*2 + 1];
            }
        }
    }
    __syncthreads();

    // GRU epilogue: 32 rows x 128 n; h written tf32-rounded (GEMM operand)
    #pragma unroll
    for (int i = 0; i < 16; i++) {
        int idx = i*256 + tid;
        int m = idx >> 7, n = idx & 127;
        int b = brow + m;
        int ng = nb*128 + n;
        float ir  = Gsm[m*384 + n]       + bih[ng];
        float iz  = Gsm[m*384 + 128 + n] + bih[1024 + ng];
        float inn = Gsm[m*384 + 256 + n] + bih[2048 + ng];
        const float* Sb = S + (long)b*SN;
        float hr = Sb[1024 + ng], hz = Sb[2048 + ng], hn = Sb[3072 + ng];
        float r  = 1.0f / (1.0f + expf(-(ir + hr)));
        float u  = 1.0f / (1.0f + expf(-(iz + hz)));
        float nn = tanhf(inn + r * hn);
        float hp = g_h[b*DETD + ng];
        float hnew = f2tf((1.0f - u) * nn + u * hp);
        feat_t[(long)b*FEATD + ng] = hnew;
        g_h[b*DETD + ng] = dn[b] ? 0.0f : hnew;
    }
}

// ---------------- weight prep (all RNA-rounded) ----------------
__global__ void rnd_copy_k(float* __restrict__ dst, const float* __restrict__ src, long n)
{
    long idx = (long)blockIdx.x * blockDim.x + threadIdx.x;
    if (idx < n) dst[idx] = f2tf(src[idx]);
}

__global__ void transpose_k(float* __restrict__ dst, const float* __restrict__ src, int K, int N)
{
    long idx = (long)blockIdx.x * blockDim.x + threadIdx.x;
    if (idx >= (long)K * N) return;
    int n = (int)(idx / K), k = (int)(idx % K);
    dst[idx] = f2tf(src[(long)k * N + n]);
}

__global__ void prep_whT_k(const float* __restrict__ prior_w, const float* __restrict__ prior_b,
                           const float* __restrict__ post_w,
                           const float* __restrict__ gru_whh, const float* __restrict__ gru_bhh)
{
    long idx = (long)blockIdx.x * blockDim.x + threadIdx.x;
    if (idx < (long)SN * DETD) {
        int n = (int)(idx >> 10), k = (int)(idx & 1023);
        float v;
        if (n < 512)       v = prior_w[k*512 + n];
        else if (n < 1024) v = post_w[k*512 + (n - 512)];
        else               v = gru_whh[(long)(n - 1024)*DETD + k];
        g_WhT[idx] = f2tf(v);
    }
    if (idx < SN) {
        int n = (int)idx;
        g_bh[n] = (n < 512) ? prior_b[n] : (n < 1024 ? 0.0f : gru_bhh[n - 1024]);
    }
}

__global__ void prep_w1fT_k(const float* __restrict__ dec_w1, const float* __restrict__ dec_b1,
                            const float* __restrict__ rew_w1, const float* __restrict__ rew_b1)
{
    long idx = (long)blockIdx.x * blockDim.x + threadIdx.x;
    if (idx < (long)2048 * FEATD) {
        int n = (int)(idx / FEATD), k = (int)(idx % FEATD);
        float v = (n < 1024) ? dec_w1[(long)k*1024 + n] : rew_w1[(long)k*1024 + (n - 1024)];
        g_W1fT[idx] = f2tf(v);
    }
    if (idx < 2048) {
        int n = (int)idx;
        g_b1f[n] = (n < 1024) ? dec_b1[n] : rew_b1[n - 1024];
    }
}

__global__ void prep_postEmbT_k(const float* __restrict__ post_w)
{
    long idx = (long)blockIdx.x * blockDim.x + threadIdx.x;
    if (idx >= (long)512*EMBD) return;
    int n = (int)(idx >> 10), k = (int)(idx & 1023);
    g_postEmbT[idx] = f2tf(post_w[(long)(1024 + k)*512 + n]);
}

// ---------------- batched loss kernels ----------------
__global__ void klbatch_k()
{
    int row = blockIdx.x, j = threadIdx.x;
    const float* Sr = g_S_all + (size_t)row*SN;
    const float* pe = g_post_emb + (long)row*512;
    float pm = Sr[j], pl = Sr[STOD + j];
    float qm = Sr[512 + j] + pe[j];
    float ql = Sr[768 + j] + pe[256 + j];
    float vq = expf(2.0f*ql), vp = expf(2.0f*pl);
    float d  = qm - pm;
    float kl = pl - ql + (vq + d*d) / (vp + 1e-8f) - 1.0f;

    __shared__ float red[STOD];
    red[j] = kl; __syncthreads();
    for (int s = STOD/2; s > 0; s >>= 1) {
        if (j < s) red[j] += red[j + s];
        __syncthreads();
    }
    if (j == 0) g_kl[row] = 0.5f * red[0];
}

__global__ void recon_k(const float* __restrict__ obs)
{
    int r = blockIdx.x, t = threadIdx.x;
    const float* p = g_pred + (long)r*OBSD;
    const float* o = obs + ((long)r + BB)*OBSD;
    float s = 0.0f;
    for (int i = t; i < OBSD; i += 128) { float d = p[i] - o[i]; s += d*d; }
    __shared__ float red[128];
    red[t] = s; __syncthreads();
    for (int st = 64; st > 0; st >>= 1) {
        if (t < st) red[t] += red[t + st];
        __syncthreads();
    }
    if (t == 0) g_recon[r] = red[0] / (float)OBSD;
}

__global__ void rew_k(const float* __restrict__ rewards,
                      const float* __restrict__ rew_w2, const float* __restrict__ rew_b2)
{
    int r = blockIdx.x, t = threadIdx.x;
    const float* hrow = g_H1 + (long)r*2048 + 1024;
    float s = 0.0f;
    for (int i = t; i < 1024; i += 256) s += hrow[i] * rew_w2[i];
    __shared__ float red[256];
    red[t] = s; __syncthreads();
    for (int st = 128; st > 0; st >>= 1) {
        if (t < st) red[t] += red[t + st];
        __syncthreads();
    }
    if (t == 0) {
        float pred = red[0] + rew_b2[0];
        float d = pred - rewards[r];
        g_rewl[r] = d*d;
    }
}

__global__ void final_k(float* __restrict__ out)
{
    int t = threadIdx.x;
    float a = 0, b = 0, c = 0;
    for (int i = t; i < RR; i += 256) { a += g_recon[i]; b += g_rewl[i]; c += g_kl[i]; }
    __shared__ float sa[256], sb[256], sc[256];
    sa[t] = a; sb[t] = b; sc[t] = c; __syncthreads();
    for (int s = 128; s > 0; s >>= 1) {
        if (t < s) { sa[t] += sa[t+s]; sb[t] += sb[t+s]; sc[t] += sc[t+s]; }
        __syncthreads();
    }
    if (t == 0) {
        float recon = sa[0] / (float)RR;
        float rew   = sb[0] / (float)RR;
        float kl    = sc[0] / (float)RR;
        out[0] = recon + rew + kl;
        out[1] = recon;
        out[2] = rew;
        out[3] = kl;
    }
}

// ---------------- host ----------------
#define SMEM128 ((2*128*32 + 2*128*32)*4)   // 65536
#define SMEM64  ((2*64*32  + 2*128*32)*4)   // 49152
#define SMEMGZ  ((1024 + 2*12288)*4)        // 102400

static inline void run128(const float* A, int lda, const float* B, int ldb,
                          float* C, int ldc, const float* bias,
                          int M, int N, int K, int relu, int rnd)
{
    dim3 grid(N/128, M/128);
    ca_gemm<128><<<grid, 256, SMEM128>>>(A, lda, B, ldb, C, ldc, bias, K, relu, rnd);
}
static inline void run64(const float* A, int lda, const float* B, int ldb,
                         float* C, int ldc, const float* bias,
                         int M, int N, int K, int relu, int rnd)
{
    dim3 grid(N/128, M/64);
    ca_gemm<64><<<grid, 256, SMEM64>>>(A, lda, B, ldb, C, ldc, bias, K, relu, rnd);
}

extern "C" void kernel_launch(void* const* d_in, const int* in_sizes, int n_in,
                              void* d_out, int out_size)
{
    const float* obs     = (const float*)d_in[0];
    const float* actions = (const float*)d_in[1];
    const float* rewards = (const float*)d_in[2];
    const unsigned char* dones = (const unsigned char*)d_in[3];
    const float* eps     = (const float*)d_in[4];
    const float* enc_w1  = (const float*)d_in[5];
    const float* enc_b1  = (const float*)d_in[6];
    const float* enc_w2  = (const float*)d_in[7];
    const float* enc_b2  = (const float*)d_in[8];
    const float* gru_wih = (const float*)d_in[9];
    const float* gru_whh = (const float*)d_in[10];
    const float* gru_bih = (const float*)d_in[11];
    const float* gru_bhh = (const float*)d_in[12];
    const float* prior_w = (const float*)d_in[13];
    const float* prior_b = (const float*)d_in[14];
    const float* post_w  = (const float*)d_in[15];
    const float* post_b  = (const float*)d_in[16];
    const float* dec_w1  = (const float*)d_in[17];
    const float* dec_b1  = (const float*)d_in[18];
    const float* dec_w2  = (const float*)d_in[19];
    const float* dec_b2  = (const float*)d_in[20];
    const float* rew_w1  = (const float*)d_in[21];
    const float* rew_b1  = (const float*)d_in[22];
    const float* rew_w2  = (const float*)d_in[23];
    const float* rew_b2  = (const float*)d_in[24];
    float* out = (float*)d_out;

    cudaFuncSetAttribute(ca_gemm<128>, cudaFuncAttributeMaxDynamicSharedMemorySize, SMEM128);
    cudaFuncSetAttribute(ca_gemm<64>,  cudaFuncAttributeMaxDynamicSharedMemorySize, SMEM64);
    cudaFuncSetAttribute(gzgru_k,      cudaFuncAttributeMaxDynamicSharedMemorySize, SMEMGZ);

    #define SYM(p, s) float* p; cudaGetSymbolAddress((void**)&p, s)
    SYM(p_obsr, g_obsr);     SYM(p_embh, g_embh);     SYM(p_emb, g_emb);
    SYM(p_post_emb, g_post_emb);
    SYM(p_feat, g_feat);     SYM(p_H1, g_H1);         SYM(p_pred, g_pred);
    SYM(p_S_all, g_S_all);   SYM(p_h, g_h);           SYM(p_wihR, g_wihR);
    SYM(p_WhT, g_WhT);       SYM(p_bh, g_bh);
    SYM(p_encw1T, g_encw1T); SYM(p_encw2T, g_encw2T);
    SYM(p_postEmbT, g_postEmbT); SYM(p_decw2T, g_decw2T);
    SYM(p_W1fT, g_W1fT);     SYM(p_b1f, g_b1f);
    #undef SYM

    cudaMemsetAsync(p_h, 0, (size_t)BB*DETD*sizeof(float));

    // ---- weight + input prep (RNA rounding) ----
    {
        long n;
        n = (long)RR*OBSD;
        rnd_copy_k<<<(unsigned)((n+255)/256), 256>>>(p_obsr, obs, n);
        n = (long)3*DETD*(STOD+ACTD);
        rnd_copy_k<<<(unsigned)((n+255)/256), 256>>>(p_wihR, gru_wih, n);
        n = (long)EMBD*OBSD;
        transpose_k<<<(unsigned)((n+255)/256), 256>>>(p_encw1T, enc_w1, OBSD, EMBD);
        n = (long)EMBD*EMBD;
        transpose_k<<<(unsigned)((n+255)/256), 256>>>(p_encw2T, enc_w2, EMBD, EMBD);
        n = (long)OBSD*EMBD;
        transpose_k<<<(unsigned)((n+255)/256), 256>>>(p_decw2T, dec_w2, EMBD, OBSD);
        n = (long)512*EMBD;
        prep_postEmbT_k<<<(unsigned)((n+255)/256), 256>>>(post_w);
        n = (long)SN*DETD;
        prep_whT_k<<<(unsigned)((n+255)/256), 256>>>(prior_w, prior_b, post_w, gru_whh, gru_bhh);
        n = (long)2048*FEATD;
        prep_w1fT_k<<<(unsigned)((n+255)/256), 256>>>(dec_w1, dec_b1, rew_w1, rew_b1);
    }

    // ---- Phase A: time-batched precompute ----
    run128(p_obsr, OBSD, p_encw1T, OBSD, p_embh, EMBD, enc_b1, RR, EMBD, OBSD, 1, 1);
    run128(p_embh, EMBD, p_encw2T, EMBD, p_emb, EMBD, enc_b2, RR, EMBD, EMBD, 1, 1);
    run128(p_emb, EMBD, p_postEmbT, EMBD, p_post_emb, 512, post_b, RR, 512, EMBD, 0, 0);

    // ---- Phase B: sequential recurrence (2 launches per step) ----
    for (int t = 0; t < TS; t++) {
        float* S_t = p_S_all + (size_t)t*BB*SN;
        run64(p_h, DETD, p_WhT, DETD, S_t, SN, p_bh, BB, SN, DETD, 0, 0);
        gzgru_k<<<dim3(8, 8), 256, SMEMGZ>>>(
            S_t,
            p_post_emb + (size_t)t*BB*512,
            eps + (size_t)t*BB*STOD,
            actions + (size_t)t*BB*ACTD,
            p_wihR, gru_bih,
            dones + (size_t)t*BB,
            p_feat + (size_t)t*BB*FEATD);
    }

    // ---- Phase C: batched KL + decoder / reward / losses ----
    klbatch_k<<<RR, STOD>>>();
    run128(p_feat, FEATD, p_W1fT, FEATD, p_H1, 2048, p_b1f, RR, 2048, FEATD, 1, 1);
    run128(p_H1, 2048, p_decw2T, EMBD, p_pred, OBSD, dec_b2, RR, OBSD, EMBD, 0, 0);
    recon_k<<<RR, 128>>>(obs);
    rew_k<<<RR, 256>>>(rewards, rew_w2, rew_b2);
    final_k<<<1, 256>>>(out);

    (void)in_sizes; (void)n_in; (void)out_size;
}

// round 12
// speedup vs baseline: 2.1133x; 1.5185x over previous
#include <cuda_runtime.h>
#include <cuda_bf16.h>
#include <math.h>
#include <stdint.h>

typedef __nv_bfloat16 bf16;

// ---------------- problem constants ----------------
#define TS   63
#define BB   256
#define OBSD 512
#define ACTD 32
#define EMBD 1024
#define DETD 1024
#define STOD 256
#define RR   (TS*BB)
#define FEATD (DETD+STOD)   // 1280
#define SN   4096           // S width: [prior 512 | post 512 | gh 3072]
#define KIH  320            // padded gzgru K: [z 256 | a 32 | pad 32]

// ---------------- device scratch ----------------
__device__ bf16  g_obsb[RR*OBSD];
__device__ bf16  g_embh[RR*EMBD];
__device__ bf16  g_emb [RR*EMBD];
__device__ float g_post_emb[RR*512];
__device__ bf16  g_feat[RR*FEATD];          // [h | z]
__device__ bf16  g_H1  [RR*2048];
__device__ float g_pred[RR*OBSD];
__device__ float g_S_all[(size_t)RR*SN];
__device__ bf16  g_h[BB*DETD];
__device__ float g_kl[RR];
__device__ float g_recon[RR];
__device__ float g_rewl[RR];
// weights (bf16), pre-transposed to [N,K]
__device__ bf16  g_WhT[SN*DETD];            // [prior | post_h | whh^T]
__device__ float g_bh[SN];
__device__ bf16  g_wihP[3*DETD*KIH];        // padded [3072, 320]
__device__ bf16  g_encw1T[EMBD*OBSD];
__device__ bf16  g_encw2T[EMBD*EMBD];
__device__ bf16  g_postEmbT[512*EMBD];
__device__ bf16  g_decw2T[OBSD*EMBD];
__device__ bf16  g_W1fT[2048*FEATD];
__device__ float g_b1f[2048];

__device__ __forceinline__ uint32_t pack_bf2(float a, float b) {
    __nv_bfloat162 h = __floats2bfloat162_rn(a, b);
    return *(uint32_t*)&h;
}
__device__ __forceinline__ int swz(int r, int k) {   // k = uint32 col 0..31
    return r*32 + (k ^ ((r & 7) << 2));
}
__device__ __forceinline__ void cp16(uint32_t saddr, const void* g) {
    asm volatile("cp.async.cg.shared.global [%0], [%1], 16;" :: "r"(saddr), "l"(g));
}
__device__ __forceinline__ void cp_commit() {
    asm volatile("cp.async.commit_group;" ::: "memory");
}
template<int N> __device__ __forceinline__ void cp_wait() {
    asm volatile("cp.async.wait_group %0;" :: "n"(N) : "memory");
}
#define MMA_BF16(c, a, b) \
    asm volatile( \
        "mma.sync.aligned.m16n8k16.row.col.f32.bf16.bf16.f32 " \
        "{%0,%1,%2,%3}, {%4,%5,%6,%7}, {%8,%9}, {%0,%1,%2,%3};" \
        : "+f"((c)[0]), "+f"((c)[1]), "+f"((c)[2]), "+f"((c)[3]) \
        : "r"((a)[0]), "r"((a)[1]), "r"((a)[2]), "r"((a)[3]), \
          "r"((b)[0]), "r"((b)[1]))

// ================= cp.async double-buffered bf16 GEMM =================
// C[M,N] = act(A[M,K] @ B[N,K]^T + bias); tile BM x 128; K-chunk 64 bf16
// (32 uint32/row, same swizzle as tf32 version). outbf: write bf16 outputs.
template<int BM>
__global__ void __launch_bounds__(256) ca_gemm(
    const bf16* __restrict__ A, int lda,
    const bf16* __restrict__ B, int ldb,
    void* __restrict__ Cv, int ldc,
    const float* __restrict__ bias, int K, int relu, int outbf)
{
    extern __shared__ uint32_t smem[];
    uint32_t* As = smem;               // 2 * BM*32
    uint32_t* Bs = smem + 2*BM*32;     // 2 * 128*32

    const int tid = threadIdx.x;
    const int wid = tid >> 5, lane = tid & 31;
    constexpr int WM   = BM/32;
    constexpr int WN   = 8/WM;
    constexpr int NCOL = 128/WN;
    constexpr int NAT  = NCOL/8;
    const int warp_m = wid % WM;
    const int warp_n = wid / WM;
    const int gid = lane >> 2, tig = lane & 3;
    const long brow = (long)blockIdx.y * BM;
    const long bcol = (long)blockIdx.x * 128;
    const int nch = K >> 6;

    const uint32_t as_u = (uint32_t)__cvta_generic_to_shared(As);
    const uint32_t bs_u = (uint32_t)__cvta_generic_to_shared(Bs);

    float c[2][NAT][4];
    #pragma unroll
    for (int im = 0; im < 2; im++)
        #pragma unroll
        for (int in_ = 0; in_ < NAT; in_++)
            #pragma unroll
            for (int j = 0; j < 4; j++) c[im][in_][j] = 0.0f;

    constexpr int NA = BM/32;
    int fr[NA], fkc[NA];
    #pragma unroll
    for (int i = 0; i < NA; i++) {
        int lin = i*256 + tid;
        fr[i]  = lin >> 3;
        fkc[i] = (lin & 7) << 2;       // uint32 col
    }
    int gr[4], gkc[4];
    #pragma unroll
    for (int i = 0; i < 4; i++) {
        int lin = i*256 + tid;
        gr[i]  = lin >> 3;
        gkc[i] = (lin & 7) << 2;
    }

    #define CA_ISSUE(cc)                                                           \
    do {                                                                           \
        int k0 = (cc) << 6; int buf = (cc) & 1;                                    \
        _Pragma("unroll")                                                          \
        for (int i = 0; i < NA; i++)                                               \
            cp16(as_u + (uint32_t)(buf*BM*32 + swz(fr[i], fkc[i]))*4,              \
                 A + (brow + fr[i])*(long)lda + k0 + fkc[i]*2);                    \
        _Pragma("unroll")                                                          \
        for (int i = 0; i < 4; i++)                                                \
            cp16(bs_u + (uint32_t)(buf*128*32 + swz(gr[i], gkc[i]))*4,             \
                 B + (bcol + gr[i])*(long)ldb + k0 + gkc[i]*2);                    \
        cp_commit();                                                               \
    } while (0)

    CA_ISSUE(0);

    for (int cch = 0; cch < nch; cch++) {
        if (cch + 1 < nch) { CA_ISSUE(cch + 1); cp_wait<1>(); }
        else               { cp_wait<0>(); }
        __syncthreads();

        const uint32_t* Ap = As + (cch & 1)*BM*32;
        const uint32_t* Bp = Bs + (cch & 1)*128*32;

        #pragma unroll
        for (int kb = 0; kb < 4; kb++) {
            const int kk = kb*8 + tig;
            uint32_t af[2][4];
            #pragma unroll
            for (int ia = 0; ia < 2; ia++) {
                int m0 = warp_m*32 + ia*16 + gid;
                int x  = (m0 & 7) << 2;
                af[ia][0] = Ap[m0*32     + (kk     ^ x)];
                af[ia][1] = Ap[(m0+8)*32 + (kk     ^ x)];
                af[ia][2] = Ap[m0*32     + ((kk+4) ^ x)];
                af[ia][3] = Ap[(m0+8)*32 + ((kk+4) ^ x)];
            }
            uint32_t bf[NAT][2];
            #pragma unroll
            for (int nb = 0; nb < NAT; nb++) {
                int n = warp_n*NCOL + nb*8 + gid;
                int x = (n & 7) << 2;
                bf[nb][0] = Bp[n*32 + (kk     ^ x)];
                bf[nb][1] = Bp[n*32 + ((kk+4) ^ x)];
            }
            #pragma unroll
            for (int im = 0; im < 2; im++)
                #pragma unroll
                for (int in_ = 0; in_ < NAT; in_++)
                    MMA_BF16(c[im][in_], af[im], bf[in_]);
        }
        __syncthreads();
    }
    #undef CA_ISSUE

    #pragma unroll
    for (int im = 0; im < 2; im++) {
        long r0 = brow + warp_m*32 + im*16 + gid;
        #pragma unroll
        for (int in_ = 0; in_ < NAT; in_++) {
            long cb = bcol + warp_n*NCOL + in_*8 + tig*2;
            #pragma unroll
            for (int half = 0; half < 2; half++) {
                long row = r0 + half*8;
                float v0 = c[im][in_][half*2 + 0];
                float v1 = c[im][in_][half*2 + 1];
                if (bias) { v0 += bias[cb]; v1 += bias[cb + 1]; }
                if (relu) { v0 = fmaxf(v0, 0.f); v1 = fmaxf(v1, 0.f); }
                if (outbf) {
                    *(uint32_t*)((bf16*)Cv + row*(long)ldc + cb) = pack_bf2(v0, v1);
                } else {
                    *(float2*)((float*)Cv + row*(long)ldc + cb) = make_float2(v0, v1);
                }
            }
        }
    }
}

// ================= fused Gz + GRU kernel (bf16) =================
// grid (nb=8, tm=8). Tile: 32 rows x 384 cols (3 gates x 128 n). K=320 (5 chunks).
__global__ void __launch_bounds__(256) gzgru_k(
    const float* __restrict__ S,          // [BB, 4096] f32
    const float* __restrict__ pe,         // [BB, 512]  f32
    const float* __restrict__ epst,       // [BB, 256]  f32
    const float* __restrict__ act,        // [BB, 32]   f32
    const bf16*  __restrict__ wihP,       // [3072, 320] bf16
    const float* __restrict__ bih,        // [3072]
    const unsigned char* __restrict__ dn, // [BB]
    bf16* __restrict__ feat_t)            // [BB, FEATD] bf16
{
    extern __shared__ uint32_t smem[];
    uint32_t* As = smem;                  // 32*32 = 1024 u32
    uint32_t* Bs = smem + 1024;           // 2 * 384*32 = 24576 u32
    float* Gsm = (float*)smem;            // alias, used post-GEMM

    const int tid = threadIdx.x;
    const int wid = tid >> 5, lane = tid & 31;
    const int gid = lane >> 2, tig = lane & 3;
    const int nb = blockIdx.x;
    const int brow = blockIdx.y * 32;
    const int nch = 5;                    // K = 320

    const uint32_t bs_u = (uint32_t)__cvta_generic_to_shared(Bs);

    float c[2][6][4];
    #pragma unroll
    for (int im = 0; im < 2; im++)
        #pragma unroll
        for (int in_ = 0; in_ < 6; in_++)
            #pragma unroll
            for (int j = 0; j < 4; j++) c[im][in_][j] = 0.0f;

    const int fr = tid >> 3, fkc = (tid & 7) << 2;   // uint32 col
    int gr[12], gkc[12];
    #pragma unroll
    for (int i = 0; i < 12; i++) {
        int lin = i*256 + tid;
        gr[i]  = lin >> 3;
        gkc[i] = (lin & 7) << 2;
    }

    #define GZ_ISSUE_B(cc)                                                         \
    do {                                                                           \
        int k0 = (cc) << 6; int buf = (cc) & 1;                                    \
        _Pragma("unroll")                                                          \
        for (int i = 0; i < 12; i++) {                                             \
            int grow = (gr[i] >> 7)*1024 + nb*128 + (gr[i] & 127);                 \
            cp16(bs_u + (uint32_t)(buf*12288 + swz(gr[i], gkc[i]))*4,              \
                 wihP + (long)grow*KIH + k0 + gkc[i]*2);                           \
        }                                                                          \
        cp_commit();                                                               \
    } while (0)

    uint4 sA;
    #define GZ_LOAD_A(cc)                                                          \
    do {                                                                           \
        int j = ((cc) << 6) + (fkc << 1);                                          \
        int b = brow + fr;                                                         \
        if (j < 256) {                                                             \
            uint32_t pk[4];                                                        \
            _Pragma("unroll")                                                      \
            for (int q = 0; q < 2; q++) {                                          \
                int jj = j + q*4;                                                  \
                float4 qm = *(const float4*)(S + (long)b*SN + 512 + jj);           \
                float4 p1 = *(const float4*)(pe + (long)b*512 + jj);               \
                float4 ql = *(const float4*)(S + (long)b*SN + 768 + jj);           \
                float4 p2 = *(const float4*)(pe + (long)b*512 + 256 + jj);         \
                float4 e  = *(const float4*)(epst + (long)b*256 + jj);             \
                float z0 = (qm.x + p1.x) + e.x * expf(ql.x + p2.x);                \
                float z1 = (qm.y + p1.y) + e.y * expf(ql.y + p2.y);                \
                float z2 = (qm.z + p1.z) + e.z * expf(ql.z + p2.z);                \
                float z3 = (qm.w + p1.w) + e.w * expf(ql.w + p2.w);                \
                pk[q*2]   = pack_bf2(z0, z1);                                      \
                pk[q*2+1] = pack_bf2(z2, z3);                                      \
            }                                                                      \
            sA = make_uint4(pk[0], pk[1], pk[2], pk[3]);                           \
            if (nb == 0) *(uint4*)(feat_t + (long)b*FEATD + DETD + j) = sA;        \
        } else if (j < 288) {                                                      \
            float4 a0 = *(const float4*)(act + (long)b*ACTD + (j - 256));          \
            float4 a1 = *(const float4*)(act + (long)b*ACTD + (j - 256) + 4);      \
            sA = make_uint4(pack_bf2(a0.x, a0.y), pack_bf2(a0.z, a0.w),            \
                            pack_bf2(a1.x, a1.y), pack_bf2(a1.z, a1.w));           \
        } else {                                                                   \
            sA = make_uint4(0, 0, 0, 0);                                           \
        }                                                                          \
    } while (0)

    GZ_ISSUE_B(0);
    GZ_LOAD_A(0);

    for (int cch = 0; cch < nch; cch++) {
        __syncthreads();
        *(uint4*)&As[swz(fr, fkc)] = sA;
        if (cch + 1 < nch) { GZ_ISSUE_B(cch + 1); cp_wait<1>(); }
        else               { cp_wait<0>(); }
        __syncthreads();
        if (cch + 1 < nch) GZ_LOAD_A(cch + 1);

        const uint32_t* Ap = As;
        const uint32_t* Bp = Bs + (cch & 1)*12288;

        #pragma unroll
        for (int kb = 0; kb < 4; kb++) {
            const int kk = kb*8 + tig;
            uint32_t af[2][4];
            #pragma unroll
            for (int ia = 0; ia < 2; ia++) {
                int m0 = ia*16 + gid;
                int x  = (m0 & 7) << 2;
                af[ia][0] = Ap[m0*32     + (kk     ^ x)];
                af[ia][1] = Ap[(m0+8)*32 + (kk     ^ x)];
                af[ia][2] = Ap[m0*32     + ((kk+4) ^ x)];
                af[ia][3] = Ap[(m0+8)*32 + ((kk+4) ^ x)];
            }
            uint32_t bf[6][2];
            #pragma unroll
            for (int nbi = 0; nbi < 6; nbi++) {
                int n = wid*48 + nbi*8 + gid;
                int x = (n & 7) << 2;
                bf[nbi][0] = Bp[n*32 + (kk     ^ x)];
                bf[nbi][1] = Bp[n*32 + ((kk+4) ^ x)];
            }
            #pragma unroll
            for (int im = 0; im < 2; im++)
                #pragma unroll
                for (int in_ = 0; in_ < 6; in_++)
                    MMA_BF16(c[im][in_], af[im], bf[in_]);
        }
    }
    __syncthreads();

    // stage G (32 x 384) into smem (f32)
    #pragma unroll
    for (int im = 0; im < 2; im++) {
        int r0 = im*16 + gid;
        #pragma unroll
        for (int in_ = 0; in_ < 6; in_++) {
            int cb = wid*48 + in_*8 + tig*2;
            #pragma unroll
            for (int half = 0; half < 2; half++) {
                int row = r0 + half*8;
                Gsm[row*384 + cb]     = c[im][in_][half*2 + 0];
                Gsm[row*384 + cb + 1] = c[im][in_][half*2 + 1];
            }
        }
    }
    __syncthreads();

    // GRU epilogue: 32 rows x 128 n; h stored bf16
    #pragma unroll
    for (int i = 0; i < 16; i++) {
        int idx = i*256 + tid;
        int m = idx >> 7, n = idx & 127;
        int b = brow + m;
        int ng = nb*128 + n;
        float ir  = Gsm[m*384 + n]       + bih[ng];
        float iz  = Gsm[m*384 + 128 + n] + bih[1024 + ng];
        float inn = Gsm[m*384 + 256 + n] + bih[2048 + ng];
        const float* Sb = S + (long)b*SN;
        float hr = Sb[1024 + ng], hz = Sb[2048 + ng], hn = Sb[3072 + ng];
        float r  = 1.0f / (1.0f + expf(-(ir + hr)));
        float u  = 1.0f / (1.0f + expf(-(iz + hz)));
        float nn = tanhf(inn + r * hn);
        float hp = __bfloat162float(g_h[b*DETD + ng]);
        float hnew = (1.0f - u) * nn + u * hp;
        bf16 hb = __float2bfloat16_rn(hnew);
        feat_t[(long)b*FEATD + ng] = hb;
        g_h[b*DETD + ng] = dn[b] ? (bf16)__float2bfloat16_rn(0.0f) : hb;
    }
}

// ---------------- weight prep (all to bf16) ----------------
__global__ void cvt_bf_k(bf16* __restrict__ dst, const float* __restrict__ src, long n)
{
    long idx = (long)blockIdx.x * blockDim.x + threadIdx.x;
    if (idx < n) dst[idx] = __float2bfloat16_rn(src[idx]);
}

__global__ void transpose_bf_k(bf16* __restrict__ dst, const float* __restrict__ src, int K, int N)
{
    long idx = (long)blockIdx.x * blockDim.x + threadIdx.x;
    if (idx >= (long)K * N) return;
    int n = (int)(idx / K), k = (int)(idx % K);
    dst[idx] = __float2bfloat16_rn(src[(long)k * N + n]);
}

__global__ void prep_whT_k(const float* __restrict__ prior_w, const float* __restrict__ prior_b,
                           const float* __restrict__ post_w,
                           const float* __restrict__ gru_whh, const float* __restrict__ gru_bhh)
{
    long idx = (long)blockIdx.x * blockDim.x + threadIdx.x;
    if (idx < (long)SN * DETD) {
        int n = (int)(idx >> 10), k = (int)(idx & 1023);
        float v;
        if (n < 512)       v = prior_w[k*512 + n];
        else if (n < 1024) v = post_w[k*512 + (n - 512)];
        else               v = gru_whh[(long)(n - 1024)*DETD + k];
        g_WhT[idx] = __float2bfloat16_rn(v);
    }
    if (idx < SN) {
        int n = (int)idx;
        g_bh[n] = (n < 512) ? prior_b[n] : (n < 1024 ? 0.0f : gru_bhh[n - 1024]);
    }
}

__global__ void prep_w1fT_k(const float* __restrict__ dec_w1, const float* __restrict__ dec_b1,
                            const float* __restrict__ rew_w1, const float* __restrict__ rew_b1)
{
    long idx = (long)blockIdx.x * blockDim.x + threadIdx.x;
    if (idx < (long)2048 * FEATD) {
        int n = (int)(idx / FEATD), k = (int)(idx % FEATD);
        float v = (n < 1024) ? dec_w1[(long)k*1024 + n] : rew_w1[(long)k*1024 + (n - 1024)];
        g_W1fT[idx] = __float2bfloat16_rn(v);
    }
    if (idx < 2048) {
        int n = (int)idx;
        g_b1f[n] = (n < 1024) ? dec_b1[n] : rew_b1[n - 1024];
    }
}

__global__ void prep_postEmbT_k(const float* __restrict__ post_w)
{
    long idx = (long)blockIdx.x * blockDim.x + threadIdx.x;
    if (idx >= (long)512*EMBD) return;
    int n = (int)(idx >> 10), k = (int)(idx & 1023);
    g_postEmbT[idx] = __float2bfloat16_rn(post_w[(long)(1024 + k)*512 + n]);
}

__global__ void prep_wihP_k(const float* __restrict__ gru_wih)
{
    long idx = (long)blockIdx.x * blockDim.x + threadIdx.x;
    if (idx >= (long)3*DETD*KIH) return;
    int n = (int)(idx / KIH), k = (int)(idx % KIH);
    g_wihP[idx] = (k < STOD+ACTD) ? __float2bfloat16_rn(gru_wih[(long)n*(STOD+ACTD) + k])
                                  : __float2bfloat16_rn(0.0f);
}

// ---------------- batched loss kernels ----------------
__global__ void klbatch_k()
{
    int row = blockIdx.x, j = threadIdx.x;
    const float* Sr = g_S_all + (size_t)row*SN;
    const float* pe = g_post_emb + (long)row*512;
    float pm = Sr[j], pl = Sr[STOD + j];
    float qm = Sr[512 + j] + pe[j];
    float ql = Sr[768 + j] + pe[256 + j];
    float vq = expf(2.0f*ql), vp = expf(2.0f*pl);
    float d  = qm - pm;
    float kl = pl - ql + (vq + d*d) / (vp + 1e-8f) - 1.0f;

    __shared__ float red[STOD];
    red[j] = kl; __syncthreads();
    for (int s = STOD/2; s > 0; s >>= 1) {
        if (j < s) red[j] += red[j + s];
        __syncthreads();
    }
    if (j == 0) g_kl[row] = 0.5f * red[0];
}

__global__ void recon_k(const float* __restrict__ obs)
{
    int r = blockIdx.x, t = threadIdx.x;
    const float* p = g_pred + (long)r*OBSD;
    const float* o = obs + ((long)r + BB)*OBSD;
    float s = 0.0f;
    for (int i = t; i < OBSD; i += 128) { float d = p[i] - o[i]; s += d*d; }
    __shared__ float red[128];
    red[t] = s; __syncthreads();
    for (int st = 64; st > 0; st >>= 1) {
        if (t < st) red[t] += red[t + st];
        __syncthreads();
    }
    if (t == 0) g_recon[r] = red[0] / (float)OBSD;
}

__global__ void rew_k(const float* __restrict__ rewards,
                      const float* __restrict__ rew_w2, const float* __restrict__ rew_b2)
{
    int r = blockIdx.x, t = threadIdx.x;
    const bf16* hrow = g_H1 + (long)r*2048 + 1024;
    float s = 0.0f;
    for (int i = t; i < 1024; i += 256) s += __bfloat162float(hrow[i]) * rew_w2[i];
    __shared__ float red[256];
    red[t] = s; __syncthreads();
    for (int st = 128; st > 0; st >>= 1) {
        if (t < st) red[t] += red[t + st];
        __syncthreads();
    }
    if (t == 0) {
        float pred = red[0] + rew_b2[0];
        float d = pred - rewards[r];
        g_rewl[r] = d*d;
    }
}

__global__ void final_k(float* __restrict__ out)
{
    int t = threadIdx.x;
    float a = 0, b = 0, c = 0;
    for (int i = t; i < RR; i += 256) { a += g_recon[i]; b += g_rewl[i]; c += g_kl[i]; }
    __shared__ float sa[256], sb[256], sc[256];
    sa[t] = a; sb[t] = b; sc[t] = c; __syncthreads();
    for (int s = 128; s > 0; s >>= 1) {
        if (t < s) { sa[t] += sa[t+s]; sb[t] += sb[t+s]; sc[t] += sc[t+s]; }
        __syncthreads();
    }
    if (t == 0) {
        float recon = sa[0] / (float)RR;
        float rew   = sb[0] / (float)RR;
        float kl    = sc[0] / (float)RR;
        out[0] = recon + rew + kl;
        out[1] = recon;
        out[2] = rew;
        out[3] = kl;
    }
}

// ---------------- host ----------------
#define SMEM128 ((2*128*32 + 2*128*32)*4)   // 65536
#define SMEM64  ((2*64*32  + 2*128*32)*4)   // 49152
#define SMEMGZ  ((1024 + 2*12288)*4)        // 102400

static inline void run128(const bf16* A, int lda, const bf16* B, int ldb,
                          void* C, int ldc, const float* bias,
                          int M, int N, int K, int relu, int outbf)
{
    dim3 grid(N/128, M/128);
    ca_gemm<128><<<grid, 256, SMEM128>>>(A, lda, B, ldb, C, ldc, bias, K, relu, outbf);
}
static inline void run64(const bf16* A, int lda, const bf16* B, int ldb,
                         void* C, int ldc, const float* bias,
                         int M, int N, int K, int relu, int outbf)
{
    dim3 grid(N/128, M/64);
    ca_gemm<64><<<grid, 256, SMEM64>>>(A, lda, B, ldb, C, ldc, bias, K, relu, outbf);
}

extern "C" void kernel_launch(void* const* d_in, const int* in_sizes, int n_in,
                              void* d_out, int out_size)
{
    const float* obs     = (const float*)d_in[0];
    const float* actions = (const float*)d_in[1];
    const float* rewards = (const float*)d_in[2];
    const unsigned char* dones = (const unsigned char*)d_in[3];
    const float* eps     = (const float*)d_in[4];
    const float* enc_w1  = (const float*)d_in[5];
    const float* enc_b1  = (const float*)d_in[6];
    const float* enc_w2  = (const float*)d_in[7];
    const float* enc_b2  = (const float*)d_in[8];
    const float* gru_wih = (const float*)d_in[9];
    const float* gru_whh = (const float*)d_in[10];
    const float* gru_bih = (const float*)d_in[11];
    const float* gru_bhh = (const float*)d_in[12];
    const float* prior_w = (const float*)d_in[13];
    const float* prior_b = (const float*)d_in[14];
    const float* post_w  = (const float*)d_in[15];
    const float* post_b  = (const float*)d_in[16];
    const float* dec_w1  = (const float*)d_in[17];
    const float* dec_b1  = (const float*)d_in[18];
    const float* dec_w2  = (const float*)d_in[19];
    const float* dec_b2  = (const float*)d_in[20];
    const float* rew_w1  = (const float*)d_in[21];
    const float* rew_b1  = (const float*)d_in[22];
    const float* rew_w2  = (const float*)d_in[23];
    const float* rew_b2  = (const float*)d_in[24];
    float* out = (float*)d_out;

    cudaFuncSetAttribute(ca_gemm<128>, cudaFuncAttributeMaxDynamicSharedMemorySize, SMEM128);
    cudaFuncSetAttribute(ca_gemm<64>,  cudaFuncAttributeMaxDynamicSharedMemorySize, SMEM64);
    cudaFuncSetAttribute(gzgru_k,      cudaFuncAttributeMaxDynamicSharedMemorySize, SMEMGZ);

    bf16 *p_obsb, *p_embh, *p_emb, *p_feat, *p_H1, *p_h;
    bf16 *p_WhT, *p_wihP, *p_encw1T, *p_encw2T, *p_postEmbT, *p_decw2T, *p_W1fT;
    float *p_post_emb, *p_pred, *p_S_all, *p_bh, *p_b1f;
    cudaGetSymbolAddress((void**)&p_obsb, g_obsb);
    cudaGetSymbolAddress((void**)&p_embh, g_embh);
    cudaGetSymbolAddress((void**)&p_emb, g_emb);
    cudaGetSymbolAddress((void**)&p_feat, g_feat);
    cudaGetSymbolAddress((void**)&p_H1, g_H1);
    cudaGetSymbolAddress((void**)&p_h, g_h);
    cudaGetSymbolAddress((void**)&p_WhT, g_WhT);
    cudaGetSymbolAddress((void**)&p_wihP, g_wihP);
    cudaGetSymbolAddress((void**)&p_encw1T, g_encw1T);
    cudaGetSymbolAddress((void**)&p_encw2T, g_encw2T);
    cudaGetSymbolAddress((void**)&p_postEmbT, g_postEmbT);
    cudaGetSymbolAddress((void**)&p_decw2T, g_decw2T);
    cudaGetSymbolAddress((void**)&p_W1fT, g_W1fT);
    cudaGetSymbolAddress((void**)&p_post_emb, g_post_emb);
    cudaGetSymbolAddress((void**)&p_pred, g_pred);
    cudaGetSymbolAddress((void**)&p_S_all, g_S_all);
    cudaGetSymbolAddress((void**)&p_bh, g_bh);
    cudaGetSymbolAddress((void**)&p_b1f, g_b1f);

    cudaMemsetAsync(p_h, 0, (size_t)BB*DETD*sizeof(bf16));

    // ---- weight + input prep ----
    {
        long n;
        n = (long)RR*OBSD;
        cvt_bf_k<<<(unsigned)((n+255)/256), 256>>>(p_obsb, obs, n);
        n = (long)3*DETD*KIH;
        prep_wihP_k<<<(unsigned)((n+255)/256), 256>>>(gru_wih);
        n = (long)EMBD*OBSD;
        transpose_bf_k<<<(unsigned)((n+255)/256), 256>>>(p_encw1T, enc_w1, OBSD, EMBD);
        n = (long)EMBD*EMBD;
        transpose_bf_k<<<(unsigned)((n+255)/256), 256>>>(p_encw2T, enc_w2, EMBD, EMBD);
        n = (long)OBSD*EMBD;
        transpose_bf_k<<<(unsigned)((n+255)/256), 256>>>(p_decw2T, dec_w2, EMBD, OBSD);
        n = (long)512*EMBD;
        prep_postEmbT_k<<<(unsigned)((n+255)/256), 256>>>(post_w);
        n = (long)SN*DETD;
        prep_whT_k<<<(unsigned)((n+255)/256), 256>>>(prior_w, prior_b, post_w, gru_whh, gru_bhh);
        n = (long)2048*FEATD;
        prep_w1fT_k<<<(unsigned)((n+255)/256), 256>>>(dec_w1, dec_b1, rew_w1, rew_b1);
    }

    // ---- Phase A: time-batched precompute ----
    run128(p_obsb, OBSD, p_encw1T, OBSD, p_embh, EMBD, enc_b1, RR, EMBD, OBSD, 1, 1);
    run128(p_embh, EMBD, p_encw2T, EMBD, p_emb, EMBD, enc_b2, RR, EMBD, EMBD, 1, 1);
    run128(p_emb, EMBD, p_postEmbT, EMBD, p_post_emb, 512, post_b, RR, 512, EMBD, 0, 0);

    // ---- Phase B: sequential recurrence (2 launches per step) ----
    for (int t = 0; t < TS; t++) {
        float* S_t = p_S_all + (size_t)t*BB*SN;
        run64(p_h, DETD, p_WhT, DETD, S_t, SN, p_bh, BB, SN, DETD, 0, 0);
        gzgru_k<<<dim3(8, 8), 256, SMEMGZ>>>(
            S_t,
            p_post_emb + (size_t)t*BB*512,
            eps + (size_t)t*BB*STOD,
            actions + (size_t)t*BB*ACTD,
            p_wihP, gru_bih,
            dones + (size_t)t*BB,
            p_feat + (size_t)t*BB*FEATD);
    }

    // ---- Phase C: batched KL + decoder / reward / losses ----
    klbatch_k<<<RR, STOD>>>();
    run128(p_feat, FEATD, p_W1fT, FEATD, p_H1, 2048, p_b1f, RR, 2048, FEATD, 1, 1);
    run128(p_H1, 2048, p_decw2T, EMBD, p_pred, OBSD, dec_b2, RR, OBSD, EMBD, 0, 0);
    recon_k<<<RR, 128>>>(obs);
    rew_k<<<RR, 256>>>(rewards, rew_w2, rew_b2);
    final_k<<<1, 256>>>(out);

    (void)in_sizes; (void)n_in; (void)out_size;
}